// round 3
// baseline (speedup 1.0000x reference)
#include <cuda_runtime.h>
#include <cuda_fp16.h>
#include <cstdint>

// Problem constants (fixed by the dataset)
#define N_NODES 100000
#define N_EDGES 3200000
#define D_FEAT  128

// ---------------- static scratch (no allocations allowed) ----------------
__device__ int  g_count[N_NODES];        // per-row edge counts
__device__ int  g_rowstart[N_NODES + 1]; // CSR row offsets (exclusive scan)
__device__ int  g_cursor[N_NODES];       // scatter cursors
__device__ int2 g_edges[N_EDGES];        // row-sorted {col, val_bits}
__device__ __half g_emb_h[N_NODES * D_FEAT];  // fp16 copy of embeds (25.6 MB)

#define SCAN_T 1024
#define NB ((N_NODES + SCAN_T - 1) / SCAN_T)   // 98
__device__ int g_blocksums[NB];
__device__ int g_blockoff[NB];

// ---------------- phase 0b: convert embeds fp32 -> fp16 ----------------
// 12.8M elements, 4 per thread (float4 in, half4=uint2 out)
__global__ void k_convert(const float* __restrict__ embeds) {
    int i = blockIdx.x * blockDim.x + threadIdx.x;          // float4 index
    const int n4 = N_NODES * D_FEAT / 4;
    if (i < n4) {
        float4 f = ((const float4*)embeds)[i];
        __half2 lo = __floats2half2_rn(f.x, f.y);
        __half2 hi = __floats2half2_rn(f.z, f.w);
        ((__half2*)g_emb_h)[i * 2 + 0] = lo;
        ((__half2*)g_emb_h)[i * 2 + 1] = hi;
    }
}

// ---------------- phase 1: histogram of rows ----------------
__global__ void k_hist(const int* __restrict__ rows) {
    int e = blockIdx.x * blockDim.x + threadIdx.x;
    if (e < N_EDGES) atomicAdd(&g_count[__ldcs(&rows[e])], 1);
}

// ---------------- phase 2a: per-block exclusive scan ----------------
__global__ void k_scan1() {
    __shared__ int s[SCAN_T];
    int t = threadIdx.x;
    int gid = blockIdx.x * SCAN_T + t;
    int v = (gid < N_NODES) ? g_count[gid] : 0;
    s[t] = v;
    __syncthreads();
    #pragma unroll
    for (int off = 1; off < SCAN_T; off <<= 1) {
        int add = (t >= off) ? s[t - off] : 0;
        __syncthreads();
        s[t] += add;
        __syncthreads();
    }
    if (gid < N_NODES) g_rowstart[gid] = s[t] - v;   // exclusive within block
    if (t == SCAN_T - 1) g_blocksums[blockIdx.x] = s[t];
}

// ---------------- phase 2b: scan the 98 block sums ----------------
__global__ void k_scan2() {
    __shared__ int s[128];
    int t = threadIdx.x;
    int v = (t < NB) ? g_blocksums[t] : 0;
    s[t] = v;
    __syncthreads();
    #pragma unroll
    for (int off = 1; off < 128; off <<= 1) {
        int add = (t >= off) ? s[t - off] : 0;
        __syncthreads();
        s[t] += add;
        __syncthreads();
    }
    if (t < NB) g_blockoff[t] = s[t] - v;
}

// ---------------- phase 2c: apply block offsets, init cursors ----------------
__global__ void k_scan3() {
    int i = blockIdx.x * blockDim.x + threadIdx.x;
    if (i < N_NODES) {
        int rs = g_rowstart[i] + g_blockoff[i >> 10];
        g_rowstart[i] = rs;
        g_cursor[i]   = rs;
    }
    if (i == 0) g_rowstart[N_NODES] = N_EDGES;
}

// ---------------- phase 3: scatter edges into row-sorted order ----------------
__global__ void k_scatter(const int* __restrict__ rows,
                          const int* __restrict__ cols,
                          const float* __restrict__ vals) {
    int e = blockIdx.x * blockDim.x + threadIdx.x;
    if (e < N_EDGES) {
        int r = __ldcs(&rows[e]);
        int pos = atomicAdd(&g_cursor[r], 1);
        g_edges[pos] = make_int2(__ldcs(&cols[e]), __float_as_int(__ldcs(&vals[e])));
    }
}

// ---------------- phase 4: warp-per-row gather (fp16 rows) + fp32 accum ----------------
// Each lane owns 4 features: loads 8 B (4 halves) per edge instead of 16 B.
// Gather traffic: E * 256 B = 0.8 GB, fully L2-resident (table is 25.6 MB).
__global__ void __launch_bounds__(256)
k_gather(float* __restrict__ out) {
    int warp = (blockIdx.x * blockDim.x + threadIdx.x) >> 5;
    int lane = threadIdx.x & 31;
    if (warp >= N_NODES) return;

    int start = g_rowstart[warp];
    int end   = g_rowstart[warp + 1];

    const uint2* __restrict__ emb2 = (const uint2*)g_emb_h;  // 8 B = 4 halves
    float4 acc = make_float4(0.f, 0.f, 0.f, 0.f);

    int e = start;
    for (; e + 4 <= end; e += 4) {
        int2 e0 = __ldcs(&g_edges[e + 0]);
        int2 e1 = __ldcs(&g_edges[e + 1]);
        int2 e2 = __ldcs(&g_edges[e + 2]);
        int2 e3 = __ldcs(&g_edges[e + 3]);
        uint2 h0 = emb2[e0.x * 32 + lane];
        uint2 h1 = emb2[e1.x * 32 + lane];
        uint2 h2 = emb2[e2.x * 32 + lane];
        uint2 h3 = emb2[e3.x * 32 + lane];
        float v0 = __int_as_float(e0.y);
        float v1 = __int_as_float(e1.y);
        float v2 = __int_as_float(e2.y);
        float v3 = __int_as_float(e3.y);
        {
            float2 a = __half22float2(*(__half2*)&h0.x);
            float2 b = __half22float2(*(__half2*)&h0.y);
            acc.x = fmaf(v0, a.x, acc.x); acc.y = fmaf(v0, a.y, acc.y);
            acc.z = fmaf(v0, b.x, acc.z); acc.w = fmaf(v0, b.y, acc.w);
        }
        {
            float2 a = __half22float2(*(__half2*)&h1.x);
            float2 b = __half22float2(*(__half2*)&h1.y);
            acc.x = fmaf(v1, a.x, acc.x); acc.y = fmaf(v1, a.y, acc.y);
            acc.z = fmaf(v1, b.x, acc.z); acc.w = fmaf(v1, b.y, acc.w);
        }
        {
            float2 a = __half22float2(*(__half2*)&h2.x);
            float2 b = __half22float2(*(__half2*)&h2.y);
            acc.x = fmaf(v2, a.x, acc.x); acc.y = fmaf(v2, a.y, acc.y);
            acc.z = fmaf(v2, b.x, acc.z); acc.w = fmaf(v2, b.y, acc.w);
        }
        {
            float2 a = __half22float2(*(__half2*)&h3.x);
            float2 b = __half22float2(*(__half2*)&h3.y);
            acc.x = fmaf(v3, a.x, acc.x); acc.y = fmaf(v3, a.y, acc.y);
            acc.z = fmaf(v3, b.x, acc.z); acc.w = fmaf(v3, b.y, acc.w);
        }
    }
    for (; e < end; e++) {
        int2 ed = __ldcs(&g_edges[e]);
        uint2 h = emb2[ed.x * 32 + lane];
        float v = __int_as_float(ed.y);
        float2 a = __half22float2(*(__half2*)&h.x);
        float2 b = __half22float2(*(__half2*)&h.y);
        acc.x = fmaf(v, a.x, acc.x); acc.y = fmaf(v, a.y, acc.y);
        acc.z = fmaf(v, b.x, acc.z); acc.w = fmaf(v, b.y, acc.w);
    }

    __stcs(&((float4*)out)[warp * 32 + lane], acc);
}

// ---------------- launch ----------------
extern "C" void kernel_launch(void* const* d_in, const int* in_sizes, int n_in,
                              void* d_out, int out_size) {
    const int*   rows   = (const int*)d_in[0];
    const int*   cols   = (const int*)d_in[1];
    const float* vals   = (const float*)d_in[2];
    const float* embeds = (const float*)d_in[3];
    float*       out    = (float*)d_out;

    // zero the histogram counters via capturable async memset
    void* count_ptr = nullptr;
    cudaGetSymbolAddress(&count_ptr, g_count);
    cudaMemsetAsync(count_ptr, 0, N_NODES * sizeof(int));

    const int TB = 256;
    const int n4 = N_NODES * D_FEAT / 4;
    k_convert<<<(n4 + TB - 1) / TB, TB>>>(embeds);
    k_hist<<<(N_EDGES + TB - 1) / TB, TB>>>(rows);
    k_scan1<<<NB, SCAN_T>>>();
    k_scan2<<<1, 128>>>();
    k_scan3<<<(N_NODES + TB - 1) / TB, TB>>>();
    k_scatter<<<(N_EDGES + TB - 1) / TB, TB>>>(rows, cols, vals);
    k_gather<<<(N_NODES * 32 + TB - 1) / TB, TB>>>(out);
}